// round 8
// baseline (speedup 1.0000x reference)
#include <cuda_runtime.h>
#include <math.h>
#include <stdint.h>

// Problem constants
#define BB 4
#define SS 1024
#define DD 768
#define HH 12
#define DH 64
#define NOPE 32
#define QP 384
#define KVP 512
#define KVIN 544            // KVP + ROPE
#define KVOUT 1152          // D + H*NOPE
#define EE 8
#define NS 2
#define FF 3072
#define TT (BB*SS)          // 4096 tokens

#define BM 128
#define BN 128
#define BK 32
#define NSTAGE 3
#define A_FLOATS (BM*36)
#define STAGE_FLOATS (A_FLOATS + 4608)
#define SMEM_BYTES (NSTAGE*STAGE_FLOATS*4)

// ---------------- scratch ----------------
__device__ float g_h[TT*DD];
__device__ float g_cq[TT*QP];
__device__ float g_Q[TT*DD];
__device__ float g_ckv[TT*KVIN];
__device__ float g_kvl[TT*KVP];
__device__ float g_KV[TT*KVOUT];
__device__ float g_qq[BB*HH*SS*DH];
__device__ float g_kk[BB*HH*SS*DH];
__device__ float g_vv[BB*HH*SS*DH];
__device__ float g_o[TT*DD];
__device__ float g_h2[TT*DD];      // unrounded (routing)
__device__ float g_h2r[TT*DD];     // tf32-rounded (gemms)
__device__ float g_act[2*(size_t)TT*FF];
__device__ float g_sc[2*TT*DD];
__device__ float g_contrib[2*TT*DD];
__device__ int   g_cnt[EE];
__device__ int   g_tok[EE*TT];
__device__ int   g_cidx[EE*TT];
__device__ float g_wl[EE*TT];
// pre-rounded weight copies
__device__ float g_wdq [DD*QP];
__device__ float g_wuq [QP*DD];
__device__ float g_wdkv[DD*KVIN];
__device__ float g_wukv[KVP*KVOUT];
__device__ float g_wo  [DD*DD];
__device__ float g_sfc [NS*(size_t)FF*DD];
__device__ float g_sprj[NS*(size_t)DD*FF];
__device__ float g_efc [EE*(size_t)FF*DD];
__device__ float g_eprj[EE*(size_t)DD*FF];

__device__ __forceinline__ float rnd_tf32(float f) {
    uint32_t b = __float_as_uint(f);
    uint32_t r = (b + 0xFFFu + ((b >> 13) & 1u)) & 0xFFFFE000u;
    return __uint_as_float(r);
}

__device__ __forceinline__ void mma_tf32(float c[4], const uint32_t a[4], const uint32_t b[2]) {
    asm volatile("mma.sync.aligned.m16n8k8.row.col.f32.tf32.tf32.f32 "
                 "{%0,%1,%2,%3}, {%4,%5,%6,%7}, {%8,%9}, {%0,%1,%2,%3};"
                 : "+f"(c[0]), "+f"(c[1]), "+f"(c[2]), "+f"(c[3])
                 : "r"(a[0]), "r"(a[1]), "r"(a[2]), "r"(a[3]), "r"(b[0]), "r"(b[1]));
}

__device__ __forceinline__ void cp_async16(float* smem_dst, const float* gmem_src, bool pred) {
    uint32_t s = (uint32_t)__cvta_generic_to_shared(smem_dst);
    int sz = pred ? 16 : 0;
    asm volatile("cp.async.cg.shared.global [%0], [%1], 16, %2;\n" :: "r"(s), "l"(gmem_src), "r"(sz));
}

// ---------------- weight rounding ----------------
__global__ void round_tf32_kernel(const float* __restrict__ in, float* __restrict__ out, int n) {
    int i = (blockIdx.x * blockDim.x + threadIdx.x) * 4;
    int stride = gridDim.x * blockDim.x * 4;
    for (; i < n; i += stride) {
        float4 v = *(const float4*)(in + i);
        v.x = rnd_tf32(v.x); v.y = rnd_tf32(v.y);
        v.z = rnd_tf32(v.z); v.w = rnd_tf32(v.w);
        *(float4*)(out + i) = v;
    }
}

// ---------------- block reduce ----------------
__device__ __forceinline__ float block_reduce_sum(float v, float* sh) {
    __syncthreads();
    int lane = threadIdx.x & 31, wid = threadIdx.x >> 5;
    #pragma unroll
    for (int o = 16; o; o >>= 1) v += __shfl_down_sync(0xffffffffu, v, o);
    if (lane == 0) sh[wid] = v;
    __syncthreads();
    if (threadIdx.x == 0) {
        float r = 0.f;
        int nw = blockDim.x >> 5;
        for (int i = 0; i < nw; i++) r += sh[i];
        sh[0] = r;
    }
    __syncthreads();
    return sh[0];
}

// ---------------- LayerNorm ----------------
// y: primary output (rounded to tf32 if roundY). y2 (optional): rounded copy.
__global__ void ln_kernel(const float* __restrict__ x, const float* __restrict__ w,
                          const float* __restrict__ b, float* __restrict__ y,
                          int cols, int inStride, int outStride,
                          int roundY, float* __restrict__ y2) {
    int row = blockIdx.x;
    const float* xi = x + (size_t)row * inStride;
    float* yo = y + (size_t)row * outStride;
    float* yo2 = y2 ? y2 + (size_t)row * outStride : nullptr;
    __shared__ float sh[8];
    int t = threadIdx.x;
    float s = 0.f;
    for (int j = t; j < cols; j += 256) s += xi[j];
    float mean = block_reduce_sum(s, sh) / (float)cols;
    float v = 0.f;
    for (int j = t; j < cols; j += 256) { float d = xi[j] - mean; v += d * d; }
    float var = block_reduce_sum(v, sh) / (float)cols;
    float rstd = rsqrtf(var + 1e-5f);
    for (int j = t; j < cols; j += 256) {
        float o = (xi[j] - mean) * rstd * w[j];
        if (b) o += b[j];
        yo[j] = roundY ? rnd_tf32(o) : o;
        if (yo2) yo2[j] = rnd_tf32(o);
    }
}

// ---------------- pipelined TF32 tensor-core GEMM ----------------
__global__ void __launch_bounds__(256)
gemm_tf32(const float* __restrict__ A, const float* __restrict__ Bm, float* __restrict__ C,
          int M, int N, int K, int BisNT,
          const float* __restrict__ resid, int doGelu, int doAccum, int doRound,
          const int* __restrict__ aRows, const int* __restrict__ cRows,
          const float* __restrict__ rowScale, const int* __restrict__ cntPtr,
          size_t zsA, size_t zsB, size_t zsC, int zsL) {
    extern __shared__ float smem[];
    int e = blockIdx.z;
    A  += (size_t)e * zsA;
    Bm += (size_t)e * zsB;
    C  += (size_t)e * zsC;
    if (aRows)    aRows    += (size_t)e * zsL;
    if (cRows)    cRows    += (size_t)e * zsL;
    if (rowScale) rowScale += (size_t)e * zsL;
    if (cntPtr)   cntPtr   += e;

    int Meff = M;
    if (cntPtr) { int c = *cntPtr; if (c < Meff) Meff = c; }
    int bm = blockIdx.y * BM, bn = blockIdx.x * BN;
    if (bm >= Meff) return;
    int t = threadIdx.x;
    int lane = t & 31, warp = t >> 5;
    int wm = warp & 1, wn = warp >> 1;
    int g = lane >> 2, tg = lane & 3;

    const int NT = K / BK;

    auto issue = [&](int kt) {
        int st = kt % NSTAGE;
        float* Sa = smem + st * STAGE_FLOATS;
        float* Sb = Sa + A_FLOATS;
        int k0 = kt * BK;
        #pragma unroll
        for (int i = 0; i < 4; i++) {
            int c = t + i * 256;
            int row = c >> 3, col4 = c & 7;
            int gm = bm + row;
            bool p = gm < Meff;
            int ar = p ? (aRows ? aRows[gm] : gm) : 0;
            cp_async16(Sa + row * 36 + col4 * 4, A + (size_t)ar * K + k0 + col4 * 4, p);
        }
        if (!BisNT) {
            #pragma unroll
            for (int i = 0; i < 4; i++) {
                int c = t + i * 256;
                int k = c >> 5, col4 = c & 31;
                bool p = (bn + col4 * 4) < N;
                cp_async16(Sb + k * 136 + col4 * 4, Bm + (size_t)(k0 + k) * N + bn + col4 * 4, p);
            }
        } else {
            #pragma unroll
            for (int i = 0; i < 4; i++) {
                int c = t + i * 256;
                int row = c >> 3, col4 = c & 7;
                bool p = (bn + row) < N;
                cp_async16(Sb + row * 36 + col4 * 4, Bm + (size_t)(bn + row) * K + k0 + col4 * 4, p);
            }
        }
        asm volatile("cp.async.commit_group;\n");
    };

    float acc[4][4][4];
    #pragma unroll
    for (int a = 0; a < 4; a++)
        #pragma unroll
        for (int b = 0; b < 4; b++)
            #pragma unroll
            for (int c = 0; c < 4; c++) acc[a][b][c] = 0.f;

    issue(0);
    if (NT > 1) issue(1);

    for (int kt = 0; kt < NT; kt++) {
        // wait until tile kt has landed (kt+1 may stay in flight)
        if (kt + 1 < NT) asm volatile("cp.async.wait_group 1;\n");
        else             asm volatile("cp.async.wait_group 0;\n");
        __syncthreads();
        // safe: writes stage (kt+2)%3, distinct from read stage kt%3 and in-flight (kt+1)%3
        if (kt + 2 < NT) issue(kt + 2);

        int st = kt % NSTAGE;
        const float* Sa = smem + st * STAGE_FLOATS;
        const float* Sb = Sa + A_FLOATS;
        const uint32_t* Sau = (const uint32_t*)Sa;
        const uint32_t* Sbu = (const uint32_t*)Sb;

        #pragma unroll
        for (int ks = 0; ks < 4; ks++) {
            int kb = ks * 8;
            uint32_t afr[4][4], bfr[4][2];
            #pragma unroll
            for (int mi = 0; mi < 4; mi++) {
                int mr = wm * 64 + mi * 16;
                afr[mi][0] = Sau[(mr + g) * 36 + kb + tg];
                afr[mi][1] = Sau[(mr + g + 8) * 36 + kb + tg];
                afr[mi][2] = Sau[(mr + g) * 36 + kb + tg + 4];
                afr[mi][3] = Sau[(mr + g + 8) * 36 + kb + tg + 4];
            }
            #pragma unroll
            for (int ni = 0; ni < 4; ni++) {
                int nc = wn * 32 + ni * 8;
                if (!BisNT) {
                    bfr[ni][0] = Sbu[(kb + tg) * 136 + nc + g];
                    bfr[ni][1] = Sbu[(kb + tg + 4) * 136 + nc + g];
                } else {
                    bfr[ni][0] = Sbu[(nc + g) * 36 + kb + tg];
                    bfr[ni][1] = Sbu[(nc + g) * 36 + kb + tg + 4];
                }
            }
            #pragma unroll
            for (int mi = 0; mi < 4; mi++)
                #pragma unroll
                for (int ni = 0; ni < 4; ni++)
                    mma_tf32(acc[mi][ni], afr[mi], bfr[ni]);
        }
    }

    // --- epilogue ---
    #pragma unroll
    for (int mi = 0; mi < 4; mi++) {
        #pragma unroll
        for (int hh = 0; hh < 2; hh++) {
            int m = bm + wm * 64 + mi * 16 + g + hh * 8;
            if (m >= Meff) continue;
            float scale = rowScale ? rowScale[m] : 1.f;
            int crow = cRows ? cRows[m] : m;
            #pragma unroll
            for (int ni = 0; ni < 4; ni++) {
                #pragma unroll
                for (int jj = 0; jj < 2; jj++) {
                    int col = bn + wn * 32 + ni * 8 + tg * 2 + jj;
                    if (col >= N) continue;
                    float v = acc[mi][ni][hh * 2 + jj];
                    if (doGelu) v = 0.5f * v * (1.f + erff(v * 0.70710678118654752f));
                    v *= scale;
                    if (resid) v += resid[(size_t)m * N + col];
                    if (doRound) v = rnd_tf32(v);
                    size_t oidx = (size_t)crow * N + col;
                    if (doAccum) C[oidx] += v; else C[oidx] = v;
                }
            }
        }
    }
}

// ---------------- build q/k/v with RoPE ----------------
__global__ void qkv_build() {
    int s = blockIdx.x, h = blockIdx.y, b = blockIdx.z, d = threadIdx.x;
    int i = b * SS + s;
    __shared__ float qr[32], kr[32];
    if (d < 32) {
        qr[d] = g_Q[(size_t)i * DD + h * DH + NOPE + d];
        kr[d] = g_ckv[(size_t)i * KVIN + KVP + d];
    }
    __syncthreads();
    float qv, kv;
    if (d < NOPE) {
        qv = g_Q[(size_t)i * DD + h * DH + d];
        kv = g_KV[(size_t)i * KVOUT + h * 96 + d];
    } else {
        int j = d - NOPE;
        int fi = j & 15;
        float ang = (float)s * expf(-(float)fi * (9.210340371976184f / 32.f));
        float c = cosf(ang), sn = sinf(ang);
        float qrot = (j < 16) ? -qr[j + 16] : qr[j - 16];
        float krot = (j < 16) ? -kr[j + 16] : kr[j - 16];
        qv = qr[j] * c + qrot * sn;
        kv = kr[j] * c + krot * sn;
    }
    size_t o = (((size_t)b * HH + h) * SS + s) * DH + d;
    g_qq[o] = qv;
    g_kk[o] = kv;
    g_vv[o] = g_KV[(size_t)i * KVOUT + h * 96 + NOPE + d];
}

// ---------------- flash attention ----------------
__global__ void __launch_bounds__(256) flash_attn() {
    int qt = blockIdx.x, h = blockIdx.y, b = blockIdx.z;
    int t = threadIdx.x;
    int tx = t & 15, ty = t >> 4;
    __shared__ float Qst[64][64];
    __shared__ float KP[64][72];
    const size_t bh = ((size_t)b * HH + h) * SS;
    const float* qg = g_qq + (bh + (size_t)qt * 64) * DH;
    {
        int m = t & 63, c0 = t >> 6;
        #pragma unroll
        for (int it = 0; it < 4; it++) {
            int d4 = c0 + it * 4;
            float4 v = *(const float4*)(qg + (size_t)m * DH + d4 * 4);
            Qst[d4 * 4 + 0][m] = v.x * 0.125f;
            Qst[d4 * 4 + 1][m] = v.y * 0.125f;
            Qst[d4 * 4 + 2][m] = v.z * 0.125f;
            Qst[d4 * 4 + 3][m] = v.w * 0.125f;
        }
    }
    float accO[4][4];
    float rowM[4], rowL[4];
    #pragma unroll
    for (int i = 0; i < 4; i++) {
        rowM[i] = -1e30f; rowL[i] = 0.f;
        #pragma unroll
        for (int j = 0; j < 4; j++) accO[i][j] = 0.f;
    }
    for (int kt = 0; kt <= qt; kt++) {
        const float* kg = g_kk + (bh + (size_t)kt * 64) * DH;
        __syncthreads();
        {
            int n = t & 63, c0 = t >> 6;
            #pragma unroll
            for (int it = 0; it < 4; it++) {
                int d4 = c0 + it * 4;
                float4 v = *(const float4*)(kg + (size_t)n * DH + d4 * 4);
                KP[d4 * 4 + 0][n] = v.x;
                KP[d4 * 4 + 1][n] = v.y;
                KP[d4 * 4 + 2][n] = v.z;
                KP[d4 * 4 + 3][n] = v.w;
            }
        }
        __syncthreads();
        float s[4][4];
        #pragma unroll
        for (int i = 0; i < 4; i++)
            #pragma unroll
            for (int j = 0; j < 4; j++) s[i][j] = 0.f;
        #pragma unroll 8
        for (int d = 0; d < 64; d++) {
            float4 qa = *(const float4*)&Qst[d][ty * 4];
            float4 kb = *(const float4*)&KP[d][tx * 4];
            float aa[4] = {qa.x, qa.y, qa.z, qa.w};
            float bb[4] = {kb.x, kb.y, kb.z, kb.w};
            #pragma unroll
            for (int i = 0; i < 4; i++)
                #pragma unroll
                for (int j = 0; j < 4; j++) s[i][j] += aa[i] * bb[j];
        }
        if (kt == qt) {
            #pragma unroll
            for (int i = 0; i < 4; i++)
                #pragma unroll
                for (int j = 0; j < 4; j++)
                    if (tx * 4 + j > ty * 4 + i) s[i][j] = -1e30f;
        }
        float ps[4][4];
        #pragma unroll
        for (int i = 0; i < 4; i++) {
            float tm = fmaxf(fmaxf(s[i][0], s[i][1]), fmaxf(s[i][2], s[i][3]));
            #pragma unroll
            for (int o = 8; o; o >>= 1) tm = fmaxf(tm, __shfl_xor_sync(0xffffffffu, tm, o, 16));
            float nm = fmaxf(rowM[i], tm);
            float corr = __expf(rowM[i] - nm);
            rowM[i] = nm;
            float rs = 0.f;
            #pragma unroll
            for (int j = 0; j < 4; j++) { ps[i][j] = __expf(s[i][j] - nm); rs += ps[i][j]; }
            #pragma unroll
            for (int o = 8; o; o >>= 1) rs += __shfl_xor_sync(0xffffffffu, rs, o, 16);
            rowL[i] = rowL[i] * corr + rs;
            #pragma unroll
            for (int j = 0; j < 4; j++) accO[i][j] *= corr;
        }
        __syncthreads();
        #pragma unroll
        for (int i = 0; i < 4; i++)
            *(float4*)&KP[ty * 4 + i][tx * 4] = make_float4(ps[i][0], ps[i][1], ps[i][2], ps[i][3]);
        __syncthreads();
        const float* vg = g_vv + (bh + (size_t)kt * 64) * DH;
        #pragma unroll 4
        for (int k4 = 0; k4 < 16; k4++) {
            float pav[4][4];
            #pragma unroll
            for (int i = 0; i < 4; i++)
                *(float4*)pav[i] = *(const float4*)&KP[ty * 4 + i][k4 * 4];
            #pragma unroll
            for (int kk = 0; kk < 4; kk++) {
                float4 vb = *(const float4*)(vg + (size_t)(k4 * 4 + kk) * DH + tx * 4);
                float bb[4] = {vb.x, vb.y, vb.z, vb.w};
                #pragma unroll
                for (int i = 0; i < 4; i++)
                    #pragma unroll
                    for (int j = 0; j < 4; j++) accO[i][j] += pav[i][kk] * bb[j];
            }
        }
    }
    #pragma unroll
    for (int i = 0; i < 4; i++) {
        float inv = 1.f / rowL[i];
        int m = qt * 64 + ty * 4 + i;
        float* op = g_o + ((size_t)(b * SS + m)) * DD + h * DH + tx * 4;
        op[0] = rnd_tf32(accO[i][0] * inv);
        op[1] = rnd_tf32(accO[i][1] * inv);
        op[2] = rnd_tf32(accO[i][2] * inv);
        op[3] = rnd_tf32(accO[i][3] * inv);
    }
}

// ---------------- routing (uses UNROUNDED h2) ----------------
__global__ void zero_cnt_kernel() {
    if (threadIdx.x < EE) g_cnt[threadIdx.x] = 0;
}

__global__ void route_kernel(const float* __restrict__ h2, const float* __restrict__ cent,
                             const float* __restrict__ rbias) {
    int warp = threadIdx.x >> 5, lane = threadIdx.x & 31;
    int tok = blockIdx.x * 8 + warp;
    if (tok >= TT) return;
    const float* hp = h2 + (size_t)tok * DD;
    float raw[EE];
    #pragma unroll
    for (int e = 0; e < EE; e++) {
        const float* cp = cent + e * DD;
        float s = 0.f;
        for (int j = lane; j < DD; j += 32) s += hp[j] * cp[j];
        #pragma unroll
        for (int o = 16; o; o >>= 1) s += __shfl_down_sync(0xffffffffu, s, o);
        raw[e] = __shfl_sync(0xffffffffu, s, 0);
    }
    if (lane == 0) {
        int e0 = 0;
        float b0 = raw[0] + rbias[0];
        for (int e = 1; e < EE; e++) {
            float v = raw[e] + rbias[e];
            if (v > b0) { b0 = v; e0 = e; }
        }
        int e1 = -1;
        float b1 = -3.4e38f;
        for (int e = 0; e < EE; e++) {
            if (e == e0) continue;
            float v = raw[e] + rbias[e];
            if (v > b1) { b1 = v; e1 = e; }
        }
        float w0 = 1.f / (1.f + expf(-raw[e0]));
        float w1 = 1.f / (1.f + expf(-raw[e1]));
        float inv = 1.f / (w0 + w1 + 1e-9f);
        w0 *= inv; w1 *= inv;
        int p0 = atomicAdd(&g_cnt[e0], 1);
        g_tok[e0 * TT + p0] = tok;
        g_cidx[e0 * TT + p0] = tok;
        g_wl[e0 * TT + p0] = w0;
        int p1 = atomicAdd(&g_cnt[e1], 1);
        g_tok[e1 * TT + p1] = tok;
        g_cidx[e1 * TT + p1] = TT + tok;
        g_wl[e1 * TT + p1] = w1;
    }
}

__global__ void final_add_kernel(float* __restrict__ out) {
    int idx = blockIdx.x * blockDim.x + threadIdx.x;
    if (idx < TT * DD)
        out[idx] += g_sc[idx] + g_sc[(size_t)TT * DD + idx]
                  + g_contrib[idx] + g_contrib[(size_t)TT * DD + idx];
}

// ---------------- launch ----------------
static inline dim3 ggrid(int M, int N, int Z = 1) {
    return dim3((N + BN - 1) / BN, (M + BM - 1) / BM, Z);
}

extern "C" void kernel_launch(void* const* d_in, const int* in_sizes, int n_in,
                              void* d_out, int out_size) {
    const float* x        = (const float*)d_in[0];
    const float* ln1_w    = (const float*)d_in[1];
    const float* ln2_w    = (const float*)d_in[2];
    const float* W_dq     = (const float*)d_in[3];
    const float* W_uq     = (const float*)d_in[4];
    const float* q_ln_w   = (const float*)d_in[5];
    const float* q_ln_b   = (const float*)d_in[6];
    const float* W_dkv    = (const float*)d_in[7];
    const float* W_ukv    = (const float*)d_in[8];
    const float* kv_ln_w  = (const float*)d_in[9];
    const float* kv_ln_b  = (const float*)d_in[10];
    const float* W_o      = (const float*)d_in[11];
    const float* s_fc     = (const float*)d_in[12];
    const float* s_proj   = (const float*)d_in[13];
    const float* e_fc     = (const float*)d_in[14];
    const float* e_proj   = (const float*)d_in[15];
    const float* centroids= (const float*)d_in[16];
    const float* rbias    = (const float*)d_in[17];
    float* out = (float*)d_out;

    cudaFuncSetAttribute(gemm_tf32, cudaFuncAttributeMaxDynamicSharedMemorySize, SMEM_BYTES);

    float *ph, *pcq, *pQ, *pckv, *pkvl, *pKV, *po, *ph2, *ph2r, *pact, *psc, *pcontrib, *pwl;
    float *pwdq, *pwuq, *pwdkv, *pwukv, *pwo, *psfc, *psprj, *pefc, *peprj;
    int *pcnt, *ptok, *pcidx;
    cudaGetSymbolAddress((void**)&ph, g_h);
    cudaGetSymbolAddress((void**)&pcq, g_cq);
    cudaGetSymbolAddress((void**)&pQ, g_Q);
    cudaGetSymbolAddress((void**)&pckv, g_ckv);
    cudaGetSymbolAddress((void**)&pkvl, g_kvl);
    cudaGetSymbolAddress((void**)&pKV, g_KV);
    cudaGetSymbolAddress((void**)&po, g_o);
    cudaGetSymbolAddress((void**)&ph2, g_h2);
    cudaGetSymbolAddress((void**)&ph2r, g_h2r);
    cudaGetSymbolAddress((void**)&pact, g_act);
    cudaGetSymbolAddress((void**)&psc, g_sc);
    cudaGetSymbolAddress((void**)&pcontrib, g_contrib);
    cudaGetSymbolAddress((void**)&pwl, g_wl);
    cudaGetSymbolAddress((void**)&pcnt, g_cnt);
    cudaGetSymbolAddress((void**)&ptok, g_tok);
    cudaGetSymbolAddress((void**)&pcidx, g_cidx);
    cudaGetSymbolAddress((void**)&pwdq, g_wdq);
    cudaGetSymbolAddress((void**)&pwuq, g_wuq);
    cudaGetSymbolAddress((void**)&pwdkv, g_wdkv);
    cudaGetSymbolAddress((void**)&pwukv, g_wukv);
    cudaGetSymbolAddress((void**)&pwo, g_wo);
    cudaGetSymbolAddress((void**)&psfc, g_sfc);
    cudaGetSymbolAddress((void**)&psprj, g_sprj);
    cudaGetSymbolAddress((void**)&pefc, g_efc);
    cudaGetSymbolAddress((void**)&peprj, g_eprj);

    // 0) pre-round all weights to tf32
    auto round_w = [&](const float* src, float* dst, size_t n) {
        int blocks = (int)((n / 4 + 255) / 256);
        if (blocks > 8192) blocks = 8192;
        round_tf32_kernel<<<blocks, 256>>>(src, dst, (int)n);
    };
    round_w(W_dq,  pwdq,  (size_t)DD*QP);
    round_w(W_uq,  pwuq,  (size_t)QP*DD);
    round_w(W_dkv, pwdkv, (size_t)DD*KVIN);
    round_w(W_ukv, pwukv, (size_t)KVP*KVOUT);
    round_w(W_o,   pwo,   (size_t)DD*DD);
    round_w(s_fc,  psfc,  (size_t)NS*FF*DD);
    round_w(s_proj,psprj, (size_t)NS*DD*FF);
    round_w(e_fc,  pefc,  (size_t)EE*FF*DD);
    round_w(e_proj,peprj, (size_t)EE*DD*FF);

    // 1) h = LN1(x), rounded
    ln_kernel<<<TT, 256>>>(x, ln1_w, nullptr, ph, DD, DD, DD, 1, nullptr);
    // 2) cq = LN_q(h @ W_dq), rounded
    gemm_tf32<<<ggrid(TT, QP), 256, SMEM_BYTES>>>(ph, pwdq, pcq, TT, QP, DD, 0,
        nullptr, 0, 0, 0, nullptr, nullptr, nullptr, nullptr, 0, 0, 0, 0);
    ln_kernel<<<TT, 256>>>(pcq, q_ln_w, q_ln_b, pcq, QP, QP, QP, 1, nullptr);
    // 3) Q = cq @ W_uq
    gemm_tf32<<<ggrid(TT, DD), 256, SMEM_BYTES>>>(pcq, pwuq, pQ, TT, DD, QP, 0,
        nullptr, 0, 0, 0, nullptr, nullptr, nullptr, nullptr, 0, 0, 0, 0);
    // 4) ckv = h @ W_dkv ; kv_lora = LN_kv(ckv[:, :512]), rounded
    gemm_tf32<<<ggrid(TT, KVIN), 256, SMEM_BYTES>>>(ph, pwdkv, pckv, TT, KVIN, DD, 0,
        nullptr, 0, 0, 0, nullptr, nullptr, nullptr, nullptr, 0, 0, 0, 0);
    ln_kernel<<<TT, 256>>>(pckv, kv_ln_w, kv_ln_b, pkvl, KVP, KVIN, KVP, 1, nullptr);
    // 5) KV = kv_lora @ W_ukv
    gemm_tf32<<<ggrid(TT, KVOUT), 256, SMEM_BYTES>>>(pkvl, pwukv, pKV, TT, KVOUT, KVP, 0,
        nullptr, 0, 0, 0, nullptr, nullptr, nullptr, nullptr, 0, 0, 0, 0);
    // 6) q/k/v with RoPE
    qkv_build<<<dim3(SS, HH, BB), 64>>>();
    // 7) flash attention -> g_o (tf32-rounded output)
    flash_attn<<<dim3(SS / 64, HH, BB), 256>>>();
    // 8) out = x + o @ W_o^T
    gemm_tf32<<<ggrid(TT, DD), 256, SMEM_BYTES>>>(po, pwo, out, TT, DD, DD, 1,
        x, 0, 0, 0, nullptr, nullptr, nullptr, nullptr, 0, 0, 0, 0);
    // 9) h2 = LN2(out): raw -> g_h2 (routing), rounded -> g_h2r (gemms)
    ln_kernel<<<TT, 256>>>(out, ln2_w, nullptr, ph2, DD, DD, DD, 0, ph2r);
    // 10) routing on unrounded h2
    zero_cnt_kernel<<<1, 32>>>();
    route_kernel<<<(TT + 7) / 8, 256>>>(ph2, centroids, rbias);
    // 11) shared experts (z=2)
    gemm_tf32<<<ggrid(TT, FF, NS), 256, SMEM_BYTES>>>(ph2r, psfc, pact, TT, FF, DD, 1,
        nullptr, 1, 0, 1, nullptr, nullptr, nullptr, nullptr,
        0, (size_t)FF * DD, (size_t)TT * FF, 0);
    gemm_tf32<<<ggrid(TT, DD, NS), 256, SMEM_BYTES>>>(pact, psprj, psc, TT, DD, FF, 1,
        nullptr, 0, 0, 0, nullptr, nullptr, nullptr, nullptr,
        (size_t)TT * FF, (size_t)DD * FF, (size_t)TT * DD, 0);
    // 12) routed experts (z=8, count-bounded)
    gemm_tf32<<<ggrid(TT, FF, EE), 256, SMEM_BYTES>>>(ph2r, pefc, pact, TT, FF, DD, 1,
        nullptr, 1, 0, 1, ptok, pcidx, nullptr, pcnt,
        0, (size_t)FF * DD, 0, TT);
    gemm_tf32<<<ggrid(TT, DD, EE), 256, SMEM_BYTES>>>(pact, peprj, pcontrib, TT, DD, FF, 1,
        nullptr, 0, 0, 0, pcidx, pcidx, pwl, pcnt,
        0, (size_t)DD * FF, 0, TT);
    // 13) out += sc0 + sc1 + contrib0 + contrib1
    final_add_kernel<<<(TT * DD + 255) / 256, 256>>>(out);
}

// round 9
// speedup vs baseline: 1.5662x; 1.5662x over previous
#include <cuda_runtime.h>
#include <math.h>
#include <stdint.h>

// Problem constants
#define BB 4
#define SS 1024
#define DD 768
#define HH 12
#define DH 64
#define NOPE 32
#define QP 384
#define KVP 512
#define KVIN 544            // KVP + ROPE
#define KVOUT 1152          // D + H*NOPE
#define EE 8
#define NS 2
#define FF 3072
#define TT (BB*SS)          // 4096 tokens

#define BM 128
#define BN 128
#define BK 32
#define NSTAGE 3
#define A_FLOATS (BM*36)
#define STAGE_FLOATS (A_FLOATS + 4608)
#define SMEM_BYTES (NSTAGE*STAGE_FLOATS*4)

// ---------------- scratch ----------------
__device__ float g_h[TT*DD];
__device__ float g_cq[TT*QP];
__device__ float g_Q[TT*DD];
__device__ float g_ckv[TT*KVIN];
__device__ float g_kvl[TT*KVP];
__device__ float g_KV[TT*KVOUT];
__device__ float g_qq[BB*HH*SS*DH];
__device__ float g_kk[BB*HH*SS*DH];
__device__ float g_vv[BB*HH*SS*DH];
__device__ float g_o[TT*DD];
__device__ float g_h2[TT*DD];      // unrounded (routing)
__device__ float g_h2r[TT*DD];     // tf32-rounded (gemms)
__device__ float g_act[2*(size_t)TT*FF];
__device__ float g_sc[2*TT*DD];
__device__ float g_contrib[2*TT*DD];
__device__ int   g_cnt[EE];
__device__ int   g_tok[EE*TT];
__device__ int   g_cidx[EE*TT];
__device__ float g_wl[EE*TT];
// pre-rounded SMALL weight copies (projection path only; ~8.7 MB total)
__device__ float g_wdq [DD*QP];
__device__ float g_wuq [QP*DD];
__device__ float g_wdkv[DD*KVIN];
__device__ float g_wukv[KVP*KVOUT];
__device__ float g_wo  [DD*DD];

__device__ __forceinline__ float rnd_tf32(float f) {
    uint32_t b = __float_as_uint(f);
    uint32_t r = (b + 0xFFFu + ((b >> 13) & 1u)) & 0xFFFFE000u;
    return __uint_as_float(r);
}

__device__ __forceinline__ void mma_tf32(float c[4], const uint32_t a[4], const uint32_t b[2]) {
    asm volatile("mma.sync.aligned.m16n8k8.row.col.f32.tf32.tf32.f32 "
                 "{%0,%1,%2,%3}, {%4,%5,%6,%7}, {%8,%9}, {%0,%1,%2,%3};"
                 : "+f"(c[0]), "+f"(c[1]), "+f"(c[2]), "+f"(c[3])
                 : "r"(a[0]), "r"(a[1]), "r"(a[2]), "r"(a[3]), "r"(b[0]), "r"(b[1]));
}

__device__ __forceinline__ void cp_async16(float* smem_dst, const float* gmem_src, bool pred) {
    uint32_t s = (uint32_t)__cvta_generic_to_shared(smem_dst);
    int sz = pred ? 16 : 0;
    asm volatile("cp.async.cg.shared.global [%0], [%1], 16, %2;\n" :: "r"(s), "l"(gmem_src), "r"(sz));
}

// ---------------- weight rounding (small tensors only) ----------------
__global__ void round_tf32_kernel(const float* __restrict__ in, float* __restrict__ out, int n) {
    int i = (blockIdx.x * blockDim.x + threadIdx.x) * 4;
    int stride = gridDim.x * blockDim.x * 4;
    for (; i < n; i += stride) {
        float4 v = *(const float4*)(in + i);
        v.x = rnd_tf32(v.x); v.y = rnd_tf32(v.y);
        v.z = rnd_tf32(v.z); v.w = rnd_tf32(v.w);
        *(float4*)(out + i) = v;
    }
}

// ---------------- block reduce ----------------
__device__ __forceinline__ float block_reduce_sum(float v, float* sh) {
    __syncthreads();
    int lane = threadIdx.x & 31, wid = threadIdx.x >> 5;
    #pragma unroll
    for (int o = 16; o; o >>= 1) v += __shfl_down_sync(0xffffffffu, v, o);
    if (lane == 0) sh[wid] = v;
    __syncthreads();
    if (threadIdx.x == 0) {
        float r = 0.f;
        int nw = blockDim.x >> 5;
        for (int i = 0; i < nw; i++) r += sh[i];
        sh[0] = r;
    }
    __syncthreads();
    return sh[0];
}

// ---------------- LayerNorm ----------------
__global__ void ln_kernel(const float* __restrict__ x, const float* __restrict__ w,
                          const float* __restrict__ b, float* __restrict__ y,
                          int cols, int inStride, int outStride,
                          int roundY, float* __restrict__ y2) {
    int row = blockIdx.x;
    const float* xi = x + (size_t)row * inStride;
    float* yo = y + (size_t)row * outStride;
    float* yo2 = y2 ? y2 + (size_t)row * outStride : nullptr;
    __shared__ float sh[8];
    int t = threadIdx.x;
    float s = 0.f;
    for (int j = t; j < cols; j += 256) s += xi[j];
    float mean = block_reduce_sum(s, sh) / (float)cols;
    float v = 0.f;
    for (int j = t; j < cols; j += 256) { float d = xi[j] - mean; v += d * d; }
    float var = block_reduce_sum(v, sh) / (float)cols;
    float rstd = rsqrtf(var + 1e-5f);
    for (int j = t; j < cols; j += 256) {
        float o = (xi[j] - mean) * rstd * w[j];
        if (b) o += b[j];
        yo[j] = roundY ? rnd_tf32(o) : o;
        if (yo2) yo2[j] = rnd_tf32(o);
    }
}

// ---------------- pipelined TF32 tensor-core GEMM ----------------
__global__ void __launch_bounds__(256)
gemm_tf32(const float* __restrict__ A, const float* __restrict__ Bm, float* __restrict__ C,
          int M, int N, int K, int BisNT,
          const float* __restrict__ resid, int doGelu, int doAccum, int doRound,
          const int* __restrict__ aRows, const int* __restrict__ cRows,
          const float* __restrict__ rowScale, const int* __restrict__ cntPtr,
          size_t zsA, size_t zsB, size_t zsC, int zsL) {
    extern __shared__ float smem[];
    int e = blockIdx.z;
    A  += (size_t)e * zsA;
    Bm += (size_t)e * zsB;
    C  += (size_t)e * zsC;
    if (aRows)    aRows    += (size_t)e * zsL;
    if (cRows)    cRows    += (size_t)e * zsL;
    if (rowScale) rowScale += (size_t)e * zsL;
    if (cntPtr)   cntPtr   += e;

    int Meff = M;
    if (cntPtr) { int c = *cntPtr; if (c < Meff) Meff = c; }
    int bm = blockIdx.y * BM, bn = blockIdx.x * BN;
    if (bm >= Meff) return;
    int t = threadIdx.x;
    int lane = t & 31, warp = t >> 5;
    int wm = warp & 1, wn = warp >> 1;
    int g = lane >> 2, tg = lane & 3;

    const int NT = K / BK;

    auto issue = [&](int kt) {
        int st = kt % NSTAGE;
        float* Sa = smem + st * STAGE_FLOATS;
        float* Sb = Sa + A_FLOATS;
        int k0 = kt * BK;
        #pragma unroll
        for (int i = 0; i < 4; i++) {
            int c = t + i * 256;
            int row = c >> 3, col4 = c & 7;
            int gm = bm + row;
            bool p = gm < Meff;
            int ar = p ? (aRows ? aRows[gm] : gm) : 0;
            cp_async16(Sa + row * 36 + col4 * 4, A + (size_t)ar * K + k0 + col4 * 4, p);
        }
        if (!BisNT) {
            #pragma unroll
            for (int i = 0; i < 4; i++) {
                int c = t + i * 256;
                int k = c >> 5, col4 = c & 31;
                bool p = (bn + col4 * 4) < N;
                cp_async16(Sb + k * 136 + col4 * 4, Bm + (size_t)(k0 + k) * N + bn + col4 * 4, p);
            }
        } else {
            #pragma unroll
            for (int i = 0; i < 4; i++) {
                int c = t + i * 256;
                int row = c >> 3, col4 = c & 7;
                bool p = (bn + row) < N;
                cp_async16(Sb + row * 36 + col4 * 4, Bm + (size_t)(bn + row) * K + k0 + col4 * 4, p);
            }
        }
        asm volatile("cp.async.commit_group;\n");
    };

    float acc[4][4][4];
    #pragma unroll
    for (int a = 0; a < 4; a++)
        #pragma unroll
        for (int b = 0; b < 4; b++)
            #pragma unroll
            for (int c = 0; c < 4; c++) acc[a][b][c] = 0.f;

    issue(0);
    if (NT > 1) issue(1);

    for (int kt = 0; kt < NT; kt++) {
        if (kt + 1 < NT) asm volatile("cp.async.wait_group 1;\n");
        else             asm volatile("cp.async.wait_group 0;\n");
        __syncthreads();
        if (kt + 2 < NT) issue(kt + 2);

        int st = kt % NSTAGE;
        const float* Sa = smem + st * STAGE_FLOATS;
        const float* Sb = Sa + A_FLOATS;
        const uint32_t* Sau = (const uint32_t*)Sa;
        const uint32_t* Sbu = (const uint32_t*)Sb;

        #pragma unroll
        for (int ks = 0; ks < 4; ks++) {
            int kb = ks * 8;
            uint32_t afr[4][4], bfr[4][2];
            #pragma unroll
            for (int mi = 0; mi < 4; mi++) {
                int mr = wm * 64 + mi * 16;
                afr[mi][0] = Sau[(mr + g) * 36 + kb + tg];
                afr[mi][1] = Sau[(mr + g + 8) * 36 + kb + tg];
                afr[mi][2] = Sau[(mr + g) * 36 + kb + tg + 4];
                afr[mi][3] = Sau[(mr + g + 8) * 36 + kb + tg + 4];
            }
            #pragma unroll
            for (int ni = 0; ni < 4; ni++) {
                int nc = wn * 32 + ni * 8;
                if (!BisNT) {
                    bfr[ni][0] = Sbu[(kb + tg) * 136 + nc + g];
                    bfr[ni][1] = Sbu[(kb + tg + 4) * 136 + nc + g];
                } else {
                    bfr[ni][0] = Sbu[(nc + g) * 36 + kb + tg];
                    bfr[ni][1] = Sbu[(nc + g) * 36 + kb + tg + 4];
                }
            }
            #pragma unroll
            for (int mi = 0; mi < 4; mi++)
                #pragma unroll
                for (int ni = 0; ni < 4; ni++)
                    mma_tf32(acc[mi][ni], afr[mi], bfr[ni]);
        }
    }

    // --- epilogue ---
    #pragma unroll
    for (int mi = 0; mi < 4; mi++) {
        #pragma unroll
        for (int hh = 0; hh < 2; hh++) {
            int m = bm + wm * 64 + mi * 16 + g + hh * 8;
            if (m >= Meff) continue;
            float scale = rowScale ? rowScale[m] : 1.f;
            int crow = cRows ? cRows[m] : m;
            #pragma unroll
            for (int ni = 0; ni < 4; ni++) {
                #pragma unroll
                for (int jj = 0; jj < 2; jj++) {
                    int col = bn + wn * 32 + ni * 8 + tg * 2 + jj;
                    if (col >= N) continue;
                    float v = acc[mi][ni][hh * 2 + jj];
                    if (doGelu) v = 0.5f * v * (1.f + erff(v * 0.70710678118654752f));
                    v *= scale;
                    if (resid) v += resid[(size_t)m * N + col];
                    if (doRound) v = rnd_tf32(v);
                    size_t oidx = (size_t)crow * N + col;
                    if (doAccum) C[oidx] += v; else C[oidx] = v;
                }
            }
        }
    }
}

// ---------------- build q/k/v with RoPE ----------------
__global__ void qkv_build() {
    int s = blockIdx.x, h = blockIdx.y, b = blockIdx.z, d = threadIdx.x;
    int i = b * SS + s;
    __shared__ float qr[32], kr[32];
    if (d < 32) {
        qr[d] = g_Q[(size_t)i * DD + h * DH + NOPE + d];
        kr[d] = g_ckv[(size_t)i * KVIN + KVP + d];
    }
    __syncthreads();
    float qv, kv;
    if (d < NOPE) {
        qv = g_Q[(size_t)i * DD + h * DH + d];
        kv = g_KV[(size_t)i * KVOUT + h * 96 + d];
    } else {
        int j = d - NOPE;
        int fi = j & 15;
        float ang = (float)s * expf(-(float)fi * (9.210340371976184f / 32.f));
        float c = cosf(ang), sn = sinf(ang);
        float qrot = (j < 16) ? -qr[j + 16] : qr[j - 16];
        float krot = (j < 16) ? -kr[j + 16] : kr[j - 16];
        qv = qr[j] * c + qrot * sn;
        kv = kr[j] * c + krot * sn;
    }
    size_t o = (((size_t)b * HH + h) * SS + s) * DH + d;
    g_qq[o] = qv;
    g_kk[o] = kv;
    g_vv[o] = g_KV[(size_t)i * KVOUT + h * 96 + NOPE + d];
}

// ---------------- flash attention ----------------
__global__ void __launch_bounds__(256) flash_attn() {
    int qt = blockIdx.x, h = blockIdx.y, b = blockIdx.z;
    int t = threadIdx.x;
    int tx = t & 15, ty = t >> 4;
    __shared__ float Qst[64][64];
    __shared__ float KP[64][72];
    const size_t bh = ((size_t)b * HH + h) * SS;
    const float* qg = g_qq + (bh + (size_t)qt * 64) * DH;
    {
        int m = t & 63, c0 = t >> 6;
        #pragma unroll
        for (int it = 0; it < 4; it++) {
            int d4 = c0 + it * 4;
            float4 v = *(const float4*)(qg + (size_t)m * DH + d4 * 4);
            Qst[d4 * 4 + 0][m] = v.x * 0.125f;
            Qst[d4 * 4 + 1][m] = v.y * 0.125f;
            Qst[d4 * 4 + 2][m] = v.z * 0.125f;
            Qst[d4 * 4 + 3][m] = v.w * 0.125f;
        }
    }
    float accO[4][4];
    float rowM[4], rowL[4];
    #pragma unroll
    for (int i = 0; i < 4; i++) {
        rowM[i] = -1e30f; rowL[i] = 0.f;
        #pragma unroll
        for (int j = 0; j < 4; j++) accO[i][j] = 0.f;
    }
    for (int kt = 0; kt <= qt; kt++) {
        const float* kg = g_kk + (bh + (size_t)kt * 64) * DH;
        __syncthreads();
        {
            int n = t & 63, c0 = t >> 6;
            #pragma unroll
            for (int it = 0; it < 4; it++) {
                int d4 = c0 + it * 4;
                float4 v = *(const float4*)(kg + (size_t)n * DH + d4 * 4);
                KP[d4 * 4 + 0][n] = v.x;
                KP[d4 * 4 + 1][n] = v.y;
                KP[d4 * 4 + 2][n] = v.z;
                KP[d4 * 4 + 3][n] = v.w;
            }
        }
        __syncthreads();
        float s[4][4];
        #pragma unroll
        for (int i = 0; i < 4; i++)
            #pragma unroll
            for (int j = 0; j < 4; j++) s[i][j] = 0.f;
        #pragma unroll 8
        for (int d = 0; d < 64; d++) {
            float4 qa = *(const float4*)&Qst[d][ty * 4];
            float4 kb = *(const float4*)&KP[d][tx * 4];
            float aa[4] = {qa.x, qa.y, qa.z, qa.w};
            float bb[4] = {kb.x, kb.y, kb.z, kb.w};
            #pragma unroll
            for (int i = 0; i < 4; i++)
                #pragma unroll
                for (int j = 0; j < 4; j++) s[i][j] += aa[i] * bb[j];
        }
        if (kt == qt) {
            #pragma unroll
            for (int i = 0; i < 4; i++)
                #pragma unroll
                for (int j = 0; j < 4; j++)
                    if (tx * 4 + j > ty * 4 + i) s[i][j] = -1e30f;
        }
        float ps[4][4];
        #pragma unroll
        for (int i = 0; i < 4; i++) {
            float tm = fmaxf(fmaxf(s[i][0], s[i][1]), fmaxf(s[i][2], s[i][3]));
            #pragma unroll
            for (int o = 8; o; o >>= 1) tm = fmaxf(tm, __shfl_xor_sync(0xffffffffu, tm, o, 16));
            float nm = fmaxf(rowM[i], tm);
            float corr = __expf(rowM[i] - nm);
            rowM[i] = nm;
            float rs = 0.f;
            #pragma unroll
            for (int j = 0; j < 4; j++) { ps[i][j] = __expf(s[i][j] - nm); rs += ps[i][j]; }
            #pragma unroll
            for (int o = 8; o; o >>= 1) rs += __shfl_xor_sync(0xffffffffu, rs, o, 16);
            rowL[i] = rowL[i] * corr + rs;
            #pragma unroll
            for (int j = 0; j < 4; j++) accO[i][j] *= corr;
        }
        __syncthreads();
        #pragma unroll
        for (int i = 0; i < 4; i++)
            *(float4*)&KP[ty * 4 + i][tx * 4] = make_float4(ps[i][0], ps[i][1], ps[i][2], ps[i][3]);
        __syncthreads();
        const float* vg = g_vv + (bh + (size_t)kt * 64) * DH;
        #pragma unroll 4
        for (int k4 = 0; k4 < 16; k4++) {
            float pav[4][4];
            #pragma unroll
            for (int i = 0; i < 4; i++)
                *(float4*)pav[i] = *(const float4*)&KP[ty * 4 + i][k4 * 4];
            #pragma unroll
            for (int kk = 0; kk < 4; kk++) {
                float4 vb = *(const float4*)(vg + (size_t)(k4 * 4 + kk) * DH + tx * 4);
                float bb[4] = {vb.x, vb.y, vb.z, vb.w};
                #pragma unroll
                for (int i = 0; i < 4; i++)
                    #pragma unroll
                    for (int j = 0; j < 4; j++) accO[i][j] += pav[i][kk] * bb[j];
            }
        }
    }
    #pragma unroll
    for (int i = 0; i < 4; i++) {
        float inv = 1.f / rowL[i];
        int m = qt * 64 + ty * 4 + i;
        float* op = g_o + ((size_t)(b * SS + m)) * DD + h * DH + tx * 4;
        op[0] = rnd_tf32(accO[i][0] * inv);
        op[1] = rnd_tf32(accO[i][1] * inv);
        op[2] = rnd_tf32(accO[i][2] * inv);
        op[3] = rnd_tf32(accO[i][3] * inv);
    }
}

// ---------------- routing (uses UNROUNDED h2) ----------------
__global__ void zero_cnt_kernel() {
    if (threadIdx.x < EE) g_cnt[threadIdx.x] = 0;
}

__global__ void route_kernel(const float* __restrict__ h2, const float* __restrict__ cent,
                             const float* __restrict__ rbias) {
    int warp = threadIdx.x >> 5, lane = threadIdx.x & 31;
    int tok = blockIdx.x * 8 + warp;
    if (tok >= TT) return;
    const float* hp = h2 + (size_t)tok * DD;
    float raw[EE];
    #pragma unroll
    for (int e = 0; e < EE; e++) {
        const float* cp = cent + e * DD;
        float s = 0.f;
        for (int j = lane; j < DD; j += 32) s += hp[j] * cp[j];
        #pragma unroll
        for (int o = 16; o; o >>= 1) s += __shfl_down_sync(0xffffffffu, s, o);
        raw[e] = __shfl_sync(0xffffffffu, s, 0);
    }
    if (lane == 0) {
        int e0 = 0;
        float b0 = raw[0] + rbias[0];
        for (int e = 1; e < EE; e++) {
            float v = raw[e] + rbias[e];
            if (v > b0) { b0 = v; e0 = e; }
        }
        int e1 = -1;
        float b1 = -3.4e38f;
        for (int e = 0; e < EE; e++) {
            if (e == e0) continue;
            float v = raw[e] + rbias[e];
            if (v > b1) { b1 = v; e1 = e; }
        }
        float w0 = 1.f / (1.f + expf(-raw[e0]));
        float w1 = 1.f / (1.f + expf(-raw[e1]));
        float inv = 1.f / (w0 + w1 + 1e-9f);
        w0 *= inv; w1 *= inv;
        int p0 = atomicAdd(&g_cnt[e0], 1);
        g_tok[e0 * TT + p0] = tok;
        g_cidx[e0 * TT + p0] = tok;
        g_wl[e0 * TT + p0] = w0;
        int p1 = atomicAdd(&g_cnt[e1], 1);
        g_tok[e1 * TT + p1] = tok;
        g_cidx[e1 * TT + p1] = TT + tok;
        g_wl[e1 * TT + p1] = w1;
    }
}

__global__ void final_add_kernel(float* __restrict__ out) {
    int idx = blockIdx.x * blockDim.x + threadIdx.x;
    if (idx < TT * DD)
        out[idx] += g_sc[idx] + g_sc[(size_t)TT * DD + idx]
                  + g_contrib[idx] + g_contrib[(size_t)TT * DD + idx];
}

// ---------------- launch ----------------
static inline dim3 ggrid(int M, int N, int Z = 1) {
    return dim3((N + BN - 1) / BN, (M + BM - 1) / BM, Z);
}

extern "C" void kernel_launch(void* const* d_in, const int* in_sizes, int n_in,
                              void* d_out, int out_size) {
    const float* x        = (const float*)d_in[0];
    const float* ln1_w    = (const float*)d_in[1];
    const float* ln2_w    = (const float*)d_in[2];
    const float* W_dq     = (const float*)d_in[3];
    const float* W_uq     = (const float*)d_in[4];
    const float* q_ln_w   = (const float*)d_in[5];
    const float* q_ln_b   = (const float*)d_in[6];
    const float* W_dkv    = (const float*)d_in[7];
    const float* W_ukv    = (const float*)d_in[8];
    const float* kv_ln_w  = (const float*)d_in[9];
    const float* kv_ln_b  = (const float*)d_in[10];
    const float* W_o      = (const float*)d_in[11];
    const float* s_fc     = (const float*)d_in[12];
    const float* s_proj   = (const float*)d_in[13];
    const float* e_fc     = (const float*)d_in[14];
    const float* e_proj   = (const float*)d_in[15];
    const float* centroids= (const float*)d_in[16];
    const float* rbias    = (const float*)d_in[17];
    float* out = (float*)d_out;

    cudaFuncSetAttribute(gemm_tf32, cudaFuncAttributeMaxDynamicSharedMemorySize, SMEM_BYTES);

    float *ph, *pcq, *pQ, *pckv, *pkvl, *pKV, *po, *ph2, *ph2r, *pact, *psc, *pcontrib, *pwl;
    float *pwdq, *pwuq, *pwdkv, *pwukv, *pwo;
    int *pcnt, *ptok, *pcidx;
    cudaGetSymbolAddress((void**)&ph, g_h);
    cudaGetSymbolAddress((void**)&pcq, g_cq);
    cudaGetSymbolAddress((void**)&pQ, g_Q);
    cudaGetSymbolAddress((void**)&pckv, g_ckv);
    cudaGetSymbolAddress((void**)&pkvl, g_kvl);
    cudaGetSymbolAddress((void**)&pKV, g_KV);
    cudaGetSymbolAddress((void**)&po, g_o);
    cudaGetSymbolAddress((void**)&ph2, g_h2);
    cudaGetSymbolAddress((void**)&ph2r, g_h2r);
    cudaGetSymbolAddress((void**)&pact, g_act);
    cudaGetSymbolAddress((void**)&psc, g_sc);
    cudaGetSymbolAddress((void**)&pcontrib, g_contrib);
    cudaGetSymbolAddress((void**)&pwl, g_wl);
    cudaGetSymbolAddress((void**)&pcnt, g_cnt);
    cudaGetSymbolAddress((void**)&ptok, g_tok);
    cudaGetSymbolAddress((void**)&pcidx, g_cidx);
    cudaGetSymbolAddress((void**)&pwdq, g_wdq);
    cudaGetSymbolAddress((void**)&pwuq, g_wuq);
    cudaGetSymbolAddress((void**)&pwdkv, g_wdkv);
    cudaGetSymbolAddress((void**)&pwukv, g_wukv);
    cudaGetSymbolAddress((void**)&pwo, g_wo);

    // 0) pre-round SMALL projection weights only (~8.7 MB)
    auto round_w = [&](const float* src, float* dst, size_t n) {
        int blocks = (int)((n / 4 + 255) / 256);
        round_tf32_kernel<<<blocks, 256>>>(src, dst, (int)n);
    };
    round_w(W_dq,  pwdq,  (size_t)DD*QP);
    round_w(W_uq,  pwuq,  (size_t)QP*DD);
    round_w(W_dkv, pwdkv, (size_t)DD*KVIN);
    round_w(W_ukv, pwukv, (size_t)KVP*KVOUT);
    round_w(W_o,   pwo,   (size_t)DD*DD);

    // 1) h = LN1(x), rounded
    ln_kernel<<<TT, 256>>>(x, ln1_w, nullptr, ph, DD, DD, DD, 1, nullptr);
    // 2) cq = LN_q(h @ W_dq), rounded
    gemm_tf32<<<ggrid(TT, QP), 256, SMEM_BYTES>>>(ph, pwdq, pcq, TT, QP, DD, 0,
        nullptr, 0, 0, 0, nullptr, nullptr, nullptr, nullptr, 0, 0, 0, 0);
    ln_kernel<<<TT, 256>>>(pcq, q_ln_w, q_ln_b, pcq, QP, QP, QP, 1, nullptr);
    // 3) Q = cq @ W_uq
    gemm_tf32<<<ggrid(TT, DD), 256, SMEM_BYTES>>>(pcq, pwuq, pQ, TT, DD, QP, 0,
        nullptr, 0, 0, 0, nullptr, nullptr, nullptr, nullptr, 0, 0, 0, 0);
    // 4) ckv = h @ W_dkv ; kv_lora = LN_kv(ckv[:, :512]), rounded
    gemm_tf32<<<ggrid(TT, KVIN), 256, SMEM_BYTES>>>(ph, pwdkv, pckv, TT, KVIN, DD, 0,
        nullptr, 0, 0, 0, nullptr, nullptr, nullptr, nullptr, 0, 0, 0, 0);
    ln_kernel<<<TT, 256>>>(pckv, kv_ln_w, kv_ln_b, pkvl, KVP, KVIN, KVP, 1, nullptr);
    // 5) KV = kv_lora @ W_ukv
    gemm_tf32<<<ggrid(TT, KVOUT), 256, SMEM_BYTES>>>(pkvl, pwukv, pKV, TT, KVOUT, KVP, 0,
        nullptr, 0, 0, 0, nullptr, nullptr, nullptr, nullptr, 0, 0, 0, 0);
    // 6) q/k/v with RoPE
    qkv_build<<<dim3(SS, HH, BB), 64>>>();
    // 7) flash attention -> g_o (tf32-rounded output)
    flash_attn<<<dim3(SS / 64, HH, BB), 256>>>();
    // 8) out = x + o @ W_o^T
    gemm_tf32<<<ggrid(TT, DD), 256, SMEM_BYTES>>>(po, pwo, out, TT, DD, DD, 1,
        x, 0, 0, 0, nullptr, nullptr, nullptr, nullptr, 0, 0, 0, 0);
    // 9) h2 = LN2(out): raw -> g_h2 (routing), rounded -> g_h2r (gemms)
    ln_kernel<<<TT, 256>>>(out, ln2_w, nullptr, ph2, DD, DD, DD, 0, ph2r);
    // 10) routing on unrounded h2
    zero_cnt_kernel<<<1, 32>>>();
    route_kernel<<<(TT + 7) / 8, 256>>>(ph2, centroids, rbias);
    // 11) shared experts (z=2); expert weights fed raw (truncated by mma)
    gemm_tf32<<<ggrid(TT, FF, NS), 256, SMEM_BYTES>>>(ph2r, s_fc, pact, TT, FF, DD, 1,
        nullptr, 1, 0, 1, nullptr, nullptr, nullptr, nullptr,
        0, (size_t)FF * DD, (size_t)TT * FF, 0);
    gemm_tf32<<<ggrid(TT, DD, NS), 256, SMEM_BYTES>>>(pact, s_proj, psc, TT, DD, FF, 1,
        nullptr, 0, 0, 0, nullptr, nullptr, nullptr, nullptr,
        (size_t)TT * FF, (size_t)DD * FF, (size_t)TT * DD, 0);
    // 12) routed experts (z=8, count-bounded)
    gemm_tf32<<<ggrid(TT, FF, EE), 256, SMEM_BYTES>>>(ph2r, e_fc, pact, TT, FF, DD, 1,
        nullptr, 1, 0, 1, ptok, pcidx, nullptr, pcnt,
        0, (size_t)FF * DD, 0, TT);
    gemm_tf32<<<ggrid(TT, DD, EE), 256, SMEM_BYTES>>>(pact, e_proj, pcontrib, TT, DD, FF, 1,
        nullptr, 0, 0, 0, pcidx, pcidx, pwl, pcnt,
        0, (size_t)DD * FF, 0, TT);
    // 13) out += sc0 + sc1 + contrib0 + contrib1
    final_add_kernel<<<(TT * DD + 255) / 256, 256>>>(out);
}